// round 2
// baseline (speedup 1.0000x reference)
#include <cuda_runtime.h>
#include <math.h>
#include <float.h>

// Problem constants
#define Bc   4
#define Lc   2048
#define Dc   1024
#define Hc   16
#define Fc   4096
#define dHc  64
#define BHc  64      // B*H
#define Uc   2048    // U_part (sampled keys)
#define TOPK 40      // u (selected queries)
#define MR   8192    // B*L rows

// ---------------- scratch (device globals; no allocation allowed) -------------
__device__ float g_Q [MR * Dc];
__device__ float g_K [MR * Dc];
__device__ float g_V [MR * Dc];
__device__ float g_Ks[Bc * Uc * Dc];
__device__ float g_AO[MR * Dc];
__device__ float g_X1[MR * Dc];
__device__ float g_Y1[MR * Fc];
__device__ float g_Y2[MR * Dc];
__device__ float g_M [BHc * Lc];
__device__ int   g_Mtop[BHc * TOPK];
__device__ float g_Or[BHc * TOPK * dHc];

// ---------------- generic fp32 GEMM: C = A(MxK) @ B(KxN) + bias, opt relu -----
__global__ __launch_bounds__(256) void gemm_bias_kernel(
    const float* __restrict__ A, const float* __restrict__ B,
    const float* __restrict__ bias, float* __restrict__ C,
    int M, int N, int K, int relu)
{
    __shared__ float As[8][128];
    __shared__ float Bs[8][128];
    int tid = threadIdx.x;
    int bm = blockIdx.y * 128;
    int bn = blockIdx.x * 128;
    int arow = tid >> 1;
    int acol = (tid & 1) << 2;
    int brow = tid >> 5;
    int bcol = (tid & 31) << 2;
    int tx = tid & 15, ty = tid >> 4;

    float acc[8][8];
#pragma unroll
    for (int i = 0; i < 8; i++)
#pragma unroll
        for (int j = 0; j < 8; j++) acc[i][j] = 0.f;

    const float* Ap = A + (size_t)(bm + arow) * K + acol;
    const float* Bp = B + (size_t)brow * N + bn + bcol;

    for (int k0 = 0; k0 < K; k0 += 8) {
        float4 av = *(const float4*)(Ap + k0);
        float4 bv = *(const float4*)(Bp + (size_t)k0 * N);
        As[acol + 0][arow] = av.x;
        As[acol + 1][arow] = av.y;
        As[acol + 2][arow] = av.z;
        As[acol + 3][arow] = av.w;
        *(float4*)&Bs[brow][bcol] = bv;
        __syncthreads();
#pragma unroll
        for (int kk = 0; kk < 8; kk++) {
            float a[8], b[8];
            *(float4*)(a)     = *(const float4*)&As[kk][ty * 8];
            *(float4*)(a + 4) = *(const float4*)&As[kk][ty * 8 + 4];
            *(float4*)(b)     = *(const float4*)&Bs[kk][tx * 8];
            *(float4*)(b + 4) = *(const float4*)&Bs[kk][tx * 8 + 4];
#pragma unroll
            for (int i = 0; i < 8; i++)
#pragma unroll
                for (int j = 0; j < 8; j++)
                    acc[i][j] = fmaf(a[i], b[j], acc[i][j]);
        }
        __syncthreads();
    }

#pragma unroll
    for (int i = 0; i < 8; i++) {
        int row = bm + ty * 8 + i;
#pragma unroll
        for (int j = 0; j < 8; j++) {
            int col = bn + tx * 8 + j;
            float v = acc[i][j] + bias[col];
            if (relu) v = fmaxf(v, 0.f);
            C[(size_t)row * N + col] = v;
        }
    }
}

// ---------------- gather sampled key rows: Ks[b,j,:] = K[b, idx[j], :] --------
__global__ void gather_kernel(const float* __restrict__ K, const int* __restrict__ idx,
                              float* __restrict__ Ks)
{
    int j = blockIdx.x & (Uc - 1);
    int b = blockIdx.x >> 11;
    int src = idx[j];
    const float4* s = (const float4*)(K + ((size_t)b * Lc + src) * Dc);
    float4* d = (float4*)(Ks + ((size_t)b * Uc + j) * Dc);
    d[threadIdx.x] = s[threadIdx.x];   // 256 threads * float4 = 1024 floats
}

// ---------------- streaming QK stats: M[bh,qi] = max_j QK - mean_j QK --------
__global__ __launch_bounds__(128) void qk_stats_kernel(
    const float* __restrict__ Q, const float* __restrict__ Ks, float* __restrict__ Mout)
{
    int bh = blockIdx.y;
    int b = bh >> 4, h = bh & 15;
    int q0 = blockIdx.x * 32;
    const float* qbase = Q + ((size_t)bh * Lc + q0) * 64;   // contiguous q slice
    const float* kbase = Ks + (size_t)b * Uc * Dc + h * 64;

    __shared__ float qs[64][32];
    __shared__ float ks[64][64];
    int tid = threadIdx.x;

#pragma unroll
    for (int i = 0; i < 4; i++) {
        int f4 = tid + i * 128;        // 0..511
        int qi = f4 >> 4;
        int e  = (f4 & 15) << 2;
        float4 v = *(const float4*)(qbase + (size_t)qi * 64 + e);
        qs[e + 0][qi] = v.x; qs[e + 1][qi] = v.y;
        qs[e + 2][qi] = v.z; qs[e + 3][qi] = v.w;
    }

    int ty = tid >> 4, tx = tid & 15;
    float  runMax[4] = {-FLT_MAX, -FLT_MAX, -FLT_MAX, -FLT_MAX};
    double runSum[4] = {0, 0, 0, 0};

    for (int kt = 0; kt < Uc; kt += 64) {
        __syncthreads();
#pragma unroll
        for (int i = 0; i < 8; i++) {
            int f4 = tid + i * 128;    // 0..1023
            int kj = f4 >> 4;
            int e  = (f4 & 15) << 2;
            float4 v = *(const float4*)(kbase + (size_t)(kt + kj) * Dc + e);
            ks[e + 0][kj] = v.x; ks[e + 1][kj] = v.y;
            ks[e + 2][kj] = v.z; ks[e + 3][kj] = v.w;
        }
        __syncthreads();

        float sc[4][4] = {};
#pragma unroll
        for (int e = 0; e < 64; e++) {
            float a[4], bb[4];
            *(float4*)a  = *(const float4*)&qs[e][ty * 4];
            *(float4*)bb = *(const float4*)&ks[e][tx * 4];
#pragma unroll
            for (int i = 0; i < 4; i++)
#pragma unroll
                for (int j = 0; j < 4; j++)
                    sc[i][j] = fmaf(a[i], bb[j], sc[i][j]);
        }
#pragma unroll
        for (int i = 0; i < 4; i++) {
            float mx = fmaxf(fmaxf(sc[i][0], sc[i][1]), fmaxf(sc[i][2], sc[i][3]));
            runMax[i] = fmaxf(runMax[i], mx);
            runSum[i] += (double)((sc[i][0] + sc[i][1]) + (sc[i][2] + sc[i][3]));
        }
    }

    // reduce across 16-lane half-warps (tx dimension)
#pragma unroll
    for (int off = 8; off > 0; off >>= 1) {
#pragma unroll
        for (int i = 0; i < 4; i++) {
            runMax[i] = fmaxf(runMax[i], __shfl_xor_sync(0xffffffffu, runMax[i], off));
            runSum[i] += __shfl_xor_sync(0xffffffffu, runSum[i], off);
        }
    }
    if (tx == 0) {
#pragma unroll
        for (int i = 0; i < 4; i++)
            Mout[(size_t)bh * Lc + q0 + ty * 4 + i] =
                runMax[i] - (float)(runSum[i] * (1.0 / (double)Lc));
    }
}

// ---------------- top-40 smallest M (ties -> lower index), per bh -------------
__global__ __launch_bounds__(256) void topk_kernel(const float* __restrict__ Mv,
                                                   int* __restrict__ Mtop)
{
    __shared__ float sv[Lc];
    __shared__ float rv[256];
    __shared__ int   ri[256];
    int bh = blockIdx.x, tid = threadIdx.x;
    for (int i = tid; i < Lc; i += 256) sv[i] = Mv[(size_t)bh * Lc + i];
    __syncthreads();

    for (int it = 0; it < TOPK; it++) {
        float bv = FLT_MAX; int bi = 0x7fffffff;
        for (int i = tid; i < Lc; i += 256) {
            float v = sv[i];
            if (v < bv || (v == bv && i < bi)) { bv = v; bi = i; }
        }
        rv[tid] = bv; ri[tid] = bi;
        __syncthreads();
        for (int s = 128; s > 0; s >>= 1) {
            if (tid < s) {
                float v2 = rv[tid + s]; int i2 = ri[tid + s];
                if (v2 < rv[tid] || (v2 == rv[tid] && i2 < ri[tid])) {
                    rv[tid] = v2; ri[tid] = i2;
                }
            }
            __syncthreads();
        }
        if (tid == 0) { Mtop[bh * TOPK + it] = ri[0]; sv[ri[0]] = FLT_MAX; }
        __syncthreads();
    }
}

// ---------------- sparse attention for one selected query -------------------
__global__ __launch_bounds__(128) void sparse_attn_kernel(
    const float* __restrict__ Q, const float* __restrict__ K, const float* __restrict__ V,
    const int* __restrict__ Mtop, float* __restrict__ outred)
{
    int ui = blockIdx.x, bh = blockIdx.y;
    int b = bh >> 4, h = bh & 15;
    int qi = Mtop[bh * TOPK + ui];

    __shared__ float qsh[64];
    __shared__ float wm[4], ws[4], wa[4][64];
    int tid = threadIdx.x, warp = tid >> 5, lane = tid & 31;
    if (tid < 64) qsh[tid] = Q[((size_t)bh * Lc + qi) * 64 + tid];
    __syncthreads();

    float q0v = qsh[lane], q1v = qsh[lane + 32];
    float m = -FLT_MAX, s = 0.f, a0 = 0.f, a1 = 0.f;
    const float* kb = K + (size_t)b * Lc * Dc + h * 64;
    const float* vb = V + (size_t)b * Lc * Dc + h * 64;

    for (int l = warp * 512; l < warp * 512 + 512; l++) {
        const float* kr = kb + (size_t)l * Dc;
        float p = q0v * kr[lane] + q1v * kr[lane + 32];
#pragma unroll
        for (int off = 16; off > 0; off >>= 1)
            p += __shfl_xor_sync(0xffffffffu, p, off);
        p *= 0.125f;                            // 1/sqrt(64)
        float mn = fmaxf(m, p);
        float c = expf(m - mn);
        float w = expf(p - mn);
        const float* vr = vb + (size_t)l * Dc;
        s  = s * c + w;
        a0 = a0 * c + w * vr[lane];
        a1 = a1 * c + w * vr[lane + 32];
        m = mn;
    }
    if (lane == 0) { wm[warp] = m; ws[warp] = s; }
    wa[warp][lane] = a0; wa[warp][lane + 32] = a1;
    __syncthreads();

    if (tid < 64) {
        float gm = fmaxf(fmaxf(wm[0], wm[1]), fmaxf(wm[2], wm[3]));
        float gs = 0.f, ga = 0.f;
#pragma unroll
        for (int w2 = 0; w2 < 4; w2++) {
            float f = expf(wm[w2] - gm);
            gs += ws[w2] * f;
            ga += wa[w2][tid] * f;
        }
        outred[((size_t)bh * TOPK + ui) * 64 + tid] = ga / gs;
    }
}

// ---------------- AO init with bo (the all-zero rows of full@wo) -------------
__global__ void init_bias_kernel(const float* __restrict__ bo, float* __restrict__ AO)
{
    float4 v = *(const float4*)(bo + threadIdx.x * 4);
    *(float4*)(AO + (size_t)blockIdx.x * Dc + threadIdx.x * 4) = v;
}

// ---------------- sparse output projection: AO[b,l,:] += out_red @ wo_headblk --
__global__ __launch_bounds__(256) void sparse_proj_kernel(
    const float* __restrict__ outred, const int* __restrict__ Mtop,
    const float* __restrict__ wo, float* __restrict__ AO)
{
    int ui = blockIdx.x, bh = blockIdx.y;
    int b = bh >> 4, h = bh & 15;
    int l = Mtop[bh * TOPK + ui];
    __shared__ float r[64];
    int tid = threadIdx.x;
    if (tid < 64) r[tid] = outred[((size_t)bh * TOPK + ui) * 64 + tid];
    __syncthreads();

    float acc0 = 0.f, acc1 = 0.f, acc2 = 0.f, acc3 = 0.f;
    const float* w = wo + (size_t)h * 64 * Dc + tid;
#pragma unroll 8
    for (int e = 0; e < 64; e++) {
        float re = r[e];
        const float* wr = w + (size_t)e * Dc;
        acc0 = fmaf(re, wr[0],   acc0);
        acc1 = fmaf(re, wr[256], acc1);
        acc2 = fmaf(re, wr[512], acc2);
        acc3 = fmaf(re, wr[768], acc3);
    }
    float* dst = AO + ((size_t)b * Lc + l) * Dc + tid;
    atomicAdd(dst,       acc0);
    atomicAdd(dst + 256, acc1);
    atomicAdd(dst + 512, acc2);
    atomicAdd(dst + 768, acc3);
}

// ---------------- residual add + LayerNorm ------------------------------------
__global__ __launch_bounds__(256) void add_ln_kernel(
    const float* __restrict__ X, const float* __restrict__ Y,
    const float* __restrict__ g, const float* __restrict__ be, float* __restrict__ out)
{
    int row = blockIdx.x, tid = threadIdx.x;
    __shared__ float red[256];
    float v[4];
    float s = 0.f;
#pragma unroll
    for (int c = 0; c < 4; c++) {
        size_t i = (size_t)row * Dc + tid + c * 256;
        v[c] = X[i] + Y[i];
        s += v[c];
    }
    red[tid] = s; __syncthreads();
    for (int st = 128; st > 0; st >>= 1) {
        if (tid < st) red[tid] += red[tid + st];
        __syncthreads();
    }
    float mean = red[0] * (1.f / 1024.f);
    __syncthreads();

    float s2 = 0.f;
#pragma unroll
    for (int c = 0; c < 4; c++) { float t = v[c] - mean; s2 = fmaf(t, t, s2); }
    red[tid] = s2; __syncthreads();
    for (int st = 128; st > 0; st >>= 1) {
        if (tid < st) red[tid] += red[tid + st];
        __syncthreads();
    }
    float var = red[0] * (1.f / 1024.f);
    float rstd = 1.0f / sqrtf(var + 1e-12f);

#pragma unroll
    for (int c = 0; c < 4; c++) {
        int col = tid + c * 256;
        out[(size_t)row * Dc + col] = g[col] * ((v[c] - mean) * rstd) + be[col];
    }
}

// ---------------- launch --------------------------------------------------------
extern "C" void kernel_launch(void* const* d_in, const int* in_sizes, int n_in,
                              void* d_out, int out_size)
{
    const float* x   = (const float*)d_in[0];
    const float* wq  = (const float*)d_in[1];
    const float* bq  = (const float*)d_in[2];
    const float* wk  = (const float*)d_in[3];
    const float* bk  = (const float*)d_in[4];
    const float* wv  = (const float*)d_in[5];
    const float* bv  = (const float*)d_in[6];
    const float* wo  = (const float*)d_in[7];
    const float* bo  = (const float*)d_in[8];
    const float* w1  = (const float*)d_in[9];
    const float* b1  = (const float*)d_in[10];
    const float* w2  = (const float*)d_in[11];
    const float* b2  = (const float*)d_in[12];
    const float* ga1 = (const float*)d_in[13];
    const float* be1 = (const float*)d_in[14];
    const float* ga2 = (const float*)d_in[15];
    const float* be2 = (const float*)d_in[16];
    const int*   idx = (const int*)d_in[17];
    float* out = (float*)d_out;

    float *Q, *K, *V, *Ks, *AO, *X1, *Y1, *Y2, *Mv, *Or;
    int* Mt;
    cudaGetSymbolAddress((void**)&Q,  g_Q);
    cudaGetSymbolAddress((void**)&K,  g_K);
    cudaGetSymbolAddress((void**)&V,  g_V);
    cudaGetSymbolAddress((void**)&Ks, g_Ks);
    cudaGetSymbolAddress((void**)&AO, g_AO);
    cudaGetSymbolAddress((void**)&X1, g_X1);
    cudaGetSymbolAddress((void**)&Y1, g_Y1);
    cudaGetSymbolAddress((void**)&Y2, g_Y2);
    cudaGetSymbolAddress((void**)&Mv, g_M);
    cudaGetSymbolAddress((void**)&Mt, g_Mtop);
    cudaGetSymbolAddress((void**)&Or, g_Or);

    dim3 gD(Dc / 128, MR / 128);   // (8, 64)
    dim3 gF(Fc / 128, MR / 128);   // (32, 64)

    // QKV projections
    gemm_bias_kernel<<<gD, 256>>>(x, wq, bq, Q, MR, Dc, Dc, 0);
    gemm_bias_kernel<<<gD, 256>>>(x, wk, bk, K, MR, Dc, Dc, 0);
    gemm_bias_kernel<<<gD, 256>>>(x, wv, bv, V, MR, Dc, Dc, 0);

    // ProbSparse selection
    gather_kernel<<<Bc * Uc, 256>>>(K, idx, Ks);
    qk_stats_kernel<<<dim3(Lc / 32, BHc), 128>>>(Q, Ks, Mv);
    topk_kernel<<<BHc, 256>>>(Mv, Mt);

    // Sparse attention over selected queries
    sparse_attn_kernel<<<dim3(TOPK, BHc), 128>>>(Q, K, V, Mt, Or);

    // Sparse output projection (full @ wo + bo, exploiting zero rows)
    init_bias_kernel<<<MR, 256>>>(bo, AO);
    sparse_proj_kernel<<<dim3(TOPK, BHc), 256>>>(Or, Mt, wo, AO);

    // Residual + LN1
    add_ln_kernel<<<MR, 256>>>(x, AO, ga1, be1, X1);

    // FFN
    gemm_bias_kernel<<<gF, 256>>>(X1, w1, b1, Y1, MR, Fc, Dc, 1);
    gemm_bias_kernel<<<gD, 256>>>(Y1, w2, b2, Y2, MR, Dc, Fc, 0);

    // Residual + LN2 -> output
    add_ln_kernel<<<MR, 256>>>(X1, Y2, ga2, be2, out);
}

// round 5
// speedup vs baseline: 1.5730x; 1.5730x over previous
#include <cuda_runtime.h>
#include <math.h>
#include <float.h>
#include <stdint.h>

#define Bc 4
#define Lc 2048
#define Dc 1024
#define Fc 4096
#define BHc 64
#define Uc 2048
#define TOPK 40
#define MR 8192

// ---------------- scratch --------------------------------------------------
__device__ float g_Q [MR * Dc];
__device__ float g_K [MR * Dc];
__device__ float g_V [MR * Dc];
__device__ float g_Qh[MR * Dc];
__device__ float g_Ql[MR * Dc];
__device__ float g_Xh[MR * Dc];
__device__ float g_Xl[MR * Dc];
__device__ float g_X1h[MR * Dc];
__device__ float g_X1l[MR * Dc];
__device__ float g_Y1h[MR * Fc];
__device__ float g_Y1l[MR * Fc];
__device__ float g_Ksh[BHc * Uc * 64];
__device__ float g_Ksl[BHc * Uc * 64];
__device__ float g_AO[MR * Dc];
__device__ float g_X1[MR * Dc];
__device__ float g_Y1[MR * Fc];
__device__ float g_Y2[MR * Dc];
__device__ float g_M [BHc * Lc];
__device__ int   g_Mtop[BHc * TOPK];
__device__ float g_Or[BHc * TOPK * 64];
__device__ float g_Wqh[Dc * Dc], g_Wql[Dc * Dc];
__device__ float g_Wkh[Dc * Dc], g_Wkl[Dc * Dc];
__device__ float g_Wvh[Dc * Dc], g_Wvl[Dc * Dc];
__device__ float g_W1h[Dc * Fc], g_W1l[Dc * Fc];
__device__ float g_W2h[Fc * Dc], g_W2l[Fc * Dc];

// ---------------- helpers --------------------------------------------------
__device__ __forceinline__ uint32_t s2u(const void* p) {
    uint32_t a;
    asm("{ .reg .u64 t; cvta.to.shared.u64 t, %1; cvt.u32.u64 %0, t; }" : "=r"(a) : "l"(p));
    return a;
}
__device__ __forceinline__ float f2t(float a) {
    uint32_t u;
    asm("cvt.rna.tf32.f32 %0, %1;" : "=r"(u) : "f"(a));
    return __uint_as_float(u);
}
__device__ __forceinline__ void cpa16(uint32_t dst, const void* src) {
    asm volatile("cp.async.ca.shared.global [%0], [%1], 16;" :: "r"(dst), "l"(src));
}
__device__ __forceinline__ void cpcommit() {
    asm volatile("cp.async.commit_group;");
}
template <int N>
__device__ __forceinline__ void cpwait() {
    asm volatile("cp.async.wait_group %0;" :: "n"(N));
}
// d += a * b  (m16n8k8 tf32)
__device__ __forceinline__ void mma8(float* d, const uint32_t* a, const uint32_t* b) {
    asm volatile(
        "mma.sync.aligned.m16n8k8.row.col.f32.tf32.tf32.f32 "
        "{%0,%1,%2,%3}, {%4,%5,%6,%7}, {%8,%9}, {%0,%1,%2,%3};"
        : "+f"(d[0]), "+f"(d[1]), "+f"(d[2]), "+f"(d[3])
        : "r"(a[0]), "r"(a[1]), "r"(a[2]), "r"(a[3]), "r"(b[0]), "r"(b[1]));
}

// ---------------- 3xTF32 mma.sync GEMM ------------------------------------
// C[M,N] = (Ah+Al)(M x Kd) @ ((Bh+Bl)[N,Kd])^T + bias (opt relu)
// block 256 thr, tile 128x128x32, cp.async double buffer.
// stage buffers: Ah +0, Al +18432, Bh +36864, Bl +55296 (row stride 144B=36f)
#define GST 73728
__global__ __launch_bounds__(256, 1) void gemm_mma(
    const float* __restrict__ Ah, const float* __restrict__ Al,
    const float* __restrict__ Bh, const float* __restrict__ Bl,
    const float* __restrict__ bias, float* __restrict__ C,
    int Kd, int Nd, int relu)
{
    extern __shared__ float smem[];
    uint32_t sb = s2u(smem);
    int tid = threadIdx.x, lane = tid & 31, wid = tid >> 5;
    int m0 = blockIdx.y * 128, n0 = blockIdx.x * 128;
    int wr = wid >> 1, wc = wid & 1;          // warp tile 32x64
    int NC = Kd >> 5;

    const float* gsrc[4] = { Ah + (size_t)m0 * Kd, Al + (size_t)m0 * Kd,
                             Bh + (size_t)n0 * Kd, Bl + (size_t)n0 * Kd };

    float c[2][8][4];
#pragma unroll
    for (int i = 0; i < 2; i++)
#pragma unroll
        for (int j = 0; j < 8; j++)
#pragma unroll
            for (int r = 0; r < 4; r++) c[i][j][r] = 0.f;

    int rld = tid >> 3, cld = tid & 7;        // 32 rows x 8 segs; 4 passes stride 32

    // preload stage 0
#pragma unroll
    for (int b4 = 0; b4 < 4; b4++) {
        uint32_t dst = sb + b4 * 18432 + rld * 144 + cld * 16;
        const float* src = gsrc[b4] + (size_t)rld * Kd + cld * 4;
#pragma unroll
        for (int rr = 0; rr < 4; rr++)
            cpa16(dst + rr * 32 * 144, src + (size_t)rr * 32 * Kd);
    }
    cpcommit();

    for (int ch = 0; ch < NC; ch++) {
        int s = ch & 1;
        if (ch + 1 < NC) {
            int k0 = (ch + 1) << 5;
            uint32_t stb = sb + ((ch + 1) & 1) * GST;
#pragma unroll
            for (int b4 = 0; b4 < 4; b4++) {
                uint32_t dst = stb + b4 * 18432 + rld * 144 + cld * 16;
                const float* src = gsrc[b4] + (size_t)rld * Kd + k0 + cld * 4;
#pragma unroll
                for (int rr = 0; rr < 4; rr++)
                    cpa16(dst + rr * 32 * 144, src + (size_t)rr * 32 * Kd);
            }
            cpcommit();
            cpwait<1>();
        } else {
            cpwait<0>();
        }
        __syncthreads();

        const float* sAh = smem + (s * GST) / 4;
        const float* sAl = sAh + 18432 / 4;
        const float* sBh = sAh + 36864 / 4;
        const float* sBl = sAh + 55296 / 4;
        int ar = wr * 32 + (lane >> 2);
        int bn = wc * 64 + (lane >> 2);
        int kq = lane & 3;

#pragma unroll
        for (int st = 0; st < 4; st++) {
            int k0 = st * 8 + kq;
            uint32_t ah[2][4], al[2][4], bh2[8][2], bl2[8][2];
#pragma unroll
            for (int mt = 0; mt < 2; mt++) {
                int r0 = ar + mt * 16;
                ah[mt][0] = __float_as_uint(sAh[r0 * 36 + k0]);
                ah[mt][1] = __float_as_uint(sAh[(r0 + 8) * 36 + k0]);
                ah[mt][2] = __float_as_uint(sAh[r0 * 36 + k0 + 4]);
                ah[mt][3] = __float_as_uint(sAh[(r0 + 8) * 36 + k0 + 4]);
                al[mt][0] = __float_as_uint(sAl[r0 * 36 + k0]);
                al[mt][1] = __float_as_uint(sAl[(r0 + 8) * 36 + k0]);
                al[mt][2] = __float_as_uint(sAl[r0 * 36 + k0 + 4]);
                al[mt][3] = __float_as_uint(sAl[(r0 + 8) * 36 + k0 + 4]);
            }
#pragma unroll
            for (int nt = 0; nt < 8; nt++) {
                int n = bn + nt * 8;
                bh2[nt][0] = __float_as_uint(sBh[n * 36 + k0]);
                bh2[nt][1] = __float_as_uint(sBh[n * 36 + k0 + 4]);
                bl2[nt][0] = __float_as_uint(sBl[n * 36 + k0]);
                bl2[nt][1] = __float_as_uint(sBl[n * 36 + k0 + 4]);
            }
#pragma unroll
            for (int mt = 0; mt < 2; mt++)
#pragma unroll
                for (int nt = 0; nt < 8; nt++) {
                    mma8(c[mt][nt], ah[mt], bh2[nt]);
                    mma8(c[mt][nt], ah[mt], bl2[nt]);
                    mma8(c[mt][nt], al[mt], bh2[nt]);
                }
        }
        __syncthreads();
    }

    // epilogue
#pragma unroll
    for (int mt = 0; mt < 2; mt++) {
        int row = m0 + wr * 32 + mt * 16 + (lane >> 2);
#pragma unroll
        for (int nt = 0; nt < 8; nt++) {
            int col = n0 + wc * 64 + nt * 8 + (lane & 3) * 2;
            float b0 = bias[col], b1 = bias[col + 1];
            float2 v0 = make_float2(c[mt][nt][0] + b0, c[mt][nt][1] + b1);
            float2 v1 = make_float2(c[mt][nt][2] + b0, c[mt][nt][3] + b1);
            if (relu) {
                v0.x = fmaxf(v0.x, 0.f); v0.y = fmaxf(v0.y, 0.f);
                v1.x = fmaxf(v1.x, 0.f); v1.y = fmaxf(v1.y, 0.f);
            }
            *(float2*)(C + (size_t)row * Nd + col) = v0;
            *(float2*)(C + (size_t)(row + 8) * Nd + col) = v1;
        }
    }
}

// ---------------- QK stats via mma.sync: M = rowmax - rowsum/L -------------
// block: 128 q rows x 2048 sampled keys (chunks of 64). warp tile 32x32.
// smem bytes: Qh 0 (34816), Ql 34816, Bstage 69632 + s*34816 (+17408 lo), red 139264
__global__ __launch_bounds__(256, 1) void qk_mma(
    const float* __restrict__ Qh, const float* __restrict__ Ql,
    const float* __restrict__ Ksh, const float* __restrict__ Ksl,
    float* __restrict__ Mout)
{
    extern __shared__ float smem[];
    uint32_t sb = s2u(smem);
    int tid = threadIdx.x, lane = tid & 31, wid = tid >> 5;
    int m0 = blockIdx.x * 128, bh = blockIdx.y;
    int wr = wid >> 1, wc = wid & 1;

    // load Q tile (128 x 64), row stride 68 floats
    {
        const float* qh = Qh + ((size_t)bh * Lc + m0) * 64;
        const float* ql = Ql + ((size_t)bh * Lc + m0) * 64;
#pragma unroll
        for (int i = 0; i < 8; i++) {
            int idx = tid + i * 256;
            int r = idx >> 4, cc = idx & 15;
            *(float4*)(smem + r * 68 + cc * 4) =
                *(const float4*)(qh + (size_t)r * 64 + cc * 4);
            *(float4*)(smem + 34816 / 4 + r * 68 + cc * 4) =
                *(const float4*)(ql + (size_t)r * 64 + cc * 4);
        }
    }

    const float* kh = Ksh + (size_t)bh * Uc * 64;
    const float* kl = Ksl + (size_t)bh * Uc * 64;
    int rld = tid >> 2, cld = tid & 3;   // 64 rows x 4 thread-segs, each does 4 segs

    // preload B stage 0: 64 rows x 64 floats, row stride 272B
    {
        uint32_t d0 = sb + 69632 + rld * 272 + cld * 16;
        const float* s0 = kh + (size_t)rld * 64 + cld * 4;
        const float* s1 = kl + (size_t)rld * 64 + cld * 4;
        cpa16(d0,       s0);
        cpa16(d0 + 64,  s0 + 16);
        cpa16(d0 + 128, s0 + 32);
        cpa16(d0 + 192, s0 + 48);
        uint32_t d1 = d0 + 17408;
        cpa16(d1,       s1);
        cpa16(d1 + 64,  s1 + 16);
        cpa16(d1 + 128, s1 + 32);
        cpa16(d1 + 192, s1 + 48);
        cpcommit();
    }
    __syncthreads();

    float rmax[2][2], rsum[2][2];
#pragma unroll
    for (int i = 0; i < 2; i++)
#pragma unroll
        for (int j = 0; j < 2; j++) { rmax[i][j] = -FLT_MAX; rsum[i][j] = 0.f; }

    for (int ch = 0; ch < 32; ch++) {
        int s = ch & 1;
        if (ch + 1 < 32) {
            int j0 = (ch + 1) * 64;
            uint32_t d0 = sb + 69632 + ((ch + 1) & 1) * 34816 + rld * 272 + cld * 16;
            const float* s0 = kh + (size_t)(j0 + rld) * 64 + cld * 4;
            const float* s1 = kl + (size_t)(j0 + rld) * 64 + cld * 4;
            cpa16(d0,       s0);
            cpa16(d0 + 64,  s0 + 16);
            cpa16(d0 + 128, s0 + 32);
            cpa16(d0 + 192, s0 + 48);
            uint32_t d1 = d0 + 17408;
            cpa16(d1,       s1);
            cpa16(d1 + 64,  s1 + 16);
            cpa16(d1 + 128, s1 + 32);
            cpa16(d1 + 192, s1 + 48);
            cpcommit();
            cpwait<1>();
        } else {
            cpwait<0>();
        }
        __syncthreads();

        const float* sQh = smem;
        const float* sQl = smem + 34816 / 4;
        const float* sBh = smem + (69632 + s * 34816) / 4;
        const float* sBl = sBh + 17408 / 4;
        int ar = wr * 32 + (lane >> 2);
        int bn = wc * 32 + (lane >> 2);
        int kq = lane & 3;

        float c[2][4][4];
#pragma unroll
        for (int i = 0; i < 2; i++)
#pragma unroll
            for (int j = 0; j < 4; j++)
#pragma unroll
                for (int r = 0; r < 4; r++) c[i][j][r] = 0.f;

#pragma unroll
        for (int st = 0; st < 8; st++) {
            int k0 = st * 8 + kq;
            uint32_t ah[2][4], al[2][4], bh2[4][2], bl2[4][2];
#pragma unroll
            for (int mt = 0; mt < 2; mt++) {
                int r0 = ar + mt * 16;
                ah[mt][0] = __float_as_uint(sQh[r0 * 68 + k0]);
                ah[mt][1] = __float_as_uint(sQh[(r0 + 8) * 68 + k0]);
                ah[mt][2] = __float_as_uint(sQh[r0 * 68 + k0 + 4]);
                ah[mt][3] = __float_as_uint(sQh[(r0 + 8) * 68 + k0 + 4]);
                al[mt][0] = __float_as_uint(sQl[r0 * 68 + k0]);
                al[mt][1] = __float_as_uint(sQl[(r0 + 8) * 68 + k0]);
                al[mt][2] = __float_as_uint(sQl[r0 * 68 + k0 + 4]);
                al[mt][3] = __float_as_uint(sQl[(r0 + 8) * 68 + k0 + 4]);
            }
#pragma unroll
            for (int nt = 0; nt < 4; nt++) {
                int n = bn + nt * 8;
                bh2[nt][0] = __float_as_uint(sBh[n * 68 + k0]);
                bh2[nt][1] = __float_as_uint(sBh[n * 68 + k0 + 4]);
                bl2[nt][0] = __float_as_uint(sBl[n * 68 + k0]);
                bl2[nt][1] = __float_as_uint(sBl[n * 68 + k0 + 4]);
            }
#pragma unroll
            for (int mt = 0; mt < 2; mt++)
#pragma unroll
                for (int nt = 0; nt < 4; nt++) {
                    mma8(c[mt][nt], ah[mt], bh2[nt]);
                    mma8(c[mt][nt], ah[mt], bl2[nt]);
                    mma8(c[mt][nt], al[mt], bh2[nt]);
                }
        }

#pragma unroll
        for (int mt = 0; mt < 2; mt++)
#pragma unroll
            for (int hf = 0; hf < 2; hf++) {
                float mx = -FLT_MAX, sm = 0.f;
#pragma unroll
                for (int nt = 0; nt < 4; nt++) {
                    float v0 = c[mt][nt][hf * 2], v1 = c[mt][nt][hf * 2 + 1];
                    mx = fmaxf(mx, fmaxf(v0, v1));
                    sm += v0 + v1;
                }
                mx = fmaxf(mx, __shfl_xor_sync(0xffffffffu, mx, 1));
                sm += __shfl_xor_sync(0xffffffffu, sm, 1);
                mx = fmaxf(mx, __shfl_xor_sync(0xffffffffu, mx, 2));
                sm += __shfl_xor_sync(0xffffffffu, sm, 2);
                rmax[mt][hf] = fmaxf(rmax[mt][hf], mx);
                rsum[mt][hf] += sm;
            }
        __syncthreads();
    }

    float* red = smem + 139264 / 4;   // [2][128][2]
    if ((lane & 3) == 0) {
#pragma unroll
        for (int mt = 0; mt < 2; mt++)
#pragma unroll
            for (int hf = 0; hf < 2; hf++) {
                int row = wr * 32 + mt * 16 + (lane >> 2) + hf * 8;
                red[(wc * 128 + row) * 2 + 0] = rmax[mt][hf];
                red[(wc * 128 + row) * 2 + 1] = rsum[mt][hf];
            }
    }
    __syncthreads();
    if (tid < 128) {
        float m0v = red[tid * 2], s0v = red[tid * 2 + 1];
        float m1v = red[(128 + tid) * 2], s1v = red[(128 + tid) * 2 + 1];
        Mout[(size_t)bh * Lc + m0 + tid] =
            fmaxf(m0v, m1v) - (s0v + s1v) * (1.f / (float)Lc);
    }
}

// ---------------- transpose + split weights: W[K,N] -> Wh/Wl [N,K] ---------
__global__ void tsplit_kernel(const float* __restrict__ W, float* __restrict__ Wh,
                              float* __restrict__ Wl, int Kd, int Nd)
{
    __shared__ float t[32][33];
    int x = threadIdx.x, y = threadIdx.y;
    int n0 = blockIdx.x * 32, k0 = blockIdx.y * 32;
#pragma unroll
    for (int i = 0; i < 32; i += 8)
        t[y + i][x] = W[(size_t)(k0 + y + i) * Nd + n0 + x];
    __syncthreads();
#pragma unroll
    for (int i = 0; i < 32; i += 8) {
        float v = t[x][y + i];
        float h = f2t(v);
        size_t o = (size_t)(n0 + y + i) * Kd + k0 + x;
        Wh[o] = h;
        Wl[o] = f2t(v - h);
    }
}

// ---------------- elementwise split fp32 -> tf32 hi/lo ---------------------
__global__ void split_kernel(const float* __restrict__ src, float* __restrict__ hi,
                             float* __restrict__ lo)
{
    int i = blockIdx.x * 256 + threadIdx.x;
    float4 v = ((const float4*)src)[i];
    float4 h, l;
    h.x = f2t(v.x); l.x = f2t(v.x - h.x);
    h.y = f2t(v.y); l.y = f2t(v.y - h.y);
    h.z = f2t(v.z); l.z = f2t(v.z - h.z);
    h.w = f2t(v.w); l.w = f2t(v.w - h.w);
    ((float4*)hi)[i] = h;
    ((float4*)lo)[i] = l;
}

// ---------------- gather sampled keys + split, head-major ------------------
__global__ void gather_split_kernel(const float* __restrict__ K, const int* __restrict__ idx,
                                    float* __restrict__ Ksh, float* __restrict__ Ksl)
{
    int j = blockIdx.x, b = blockIdx.y, t = threadIdx.x;
    int src = idx[j];
    float4 v = *(const float4*)(K + ((size_t)b * Lc + src) * Dc + t * 4);
    int h = t >> 4, e = (t & 15) * 4;
    float4 hi, lo;
    hi.x = f2t(v.x); lo.x = f2t(v.x - hi.x);
    hi.y = f2t(v.y); lo.y = f2t(v.y - hi.y);
    hi.z = f2t(v.z); lo.z = f2t(v.z - hi.z);
    hi.w = f2t(v.w); lo.w = f2t(v.w - hi.w);
    size_t o = (((size_t)(b * 16 + h)) * Uc + j) * 64 + e;
    *(float4*)(Ksh + o) = hi;
    *(float4*)(Ksl + o) = lo;
}

// ---------------- top-40 smallest M (ties -> lower index) ------------------
__global__ __launch_bounds__(256) void topk_kernel(const float* __restrict__ Mv,
                                                   int* __restrict__ Mtop)
{
    __shared__ float sv[Lc];
    __shared__ float rv[256];
    __shared__ int   ri[256];
    int bh = blockIdx.x, tid = threadIdx.x;
    for (int i = tid; i < Lc; i += 256) sv[i] = Mv[(size_t)bh * Lc + i];
    __syncthreads();
    for (int it = 0; it < TOPK; it++) {
        float bv = FLT_MAX; int bi = 0x7fffffff;
        for (int i = tid; i < Lc; i += 256) {
            float v = sv[i];
            if (v < bv || (v == bv && i < bi)) { bv = v; bi = i; }
        }
        rv[tid] = bv; ri[tid] = bi;
        __syncthreads();
        for (int s = 128; s > 0; s >>= 1) {
            if (tid < s) {
                float v2 = rv[tid + s]; int i2 = ri[tid + s];
                if (v2 < rv[tid] || (v2 == rv[tid] && i2 < ri[tid])) {
                    rv[tid] = v2; ri[tid] = i2;
                }
            }
            __syncthreads();
        }
        if (tid == 0) { Mtop[bh * TOPK + it] = ri[0]; sv[ri[0]] = FLT_MAX; }
        __syncthreads();
    }
}

// ---------------- sparse attention for one selected query ------------------
__global__ __launch_bounds__(128) void sparse_attn_kernel(
    const float* __restrict__ Q, const float* __restrict__ K, const float* __restrict__ V,
    const int* __restrict__ Mtop, float* __restrict__ outred)
{
    int ui = blockIdx.x, bh = blockIdx.y;
    int b = bh >> 4, h = bh & 15;
    int qi = Mtop[bh * TOPK + ui];
    __shared__ float qsh[64];
    __shared__ float wm[4], ws[4], wa[4][64];
    int tid = threadIdx.x, warp = tid >> 5, lane = tid & 31;
    if (tid < 64) qsh[tid] = Q[((size_t)bh * Lc + qi) * 64 + tid];
    __syncthreads();
    float q0v = qsh[lane], q1v = qsh[lane + 32];
    float m = -FLT_MAX, s = 0.f, a0 = 0.f, a1 = 0.f;
    const float* kb = K + (size_t)b * Lc * Dc + h * 64;
    const float* vb = V + (size_t)b * Lc * Dc + h * 64;
    for (int l = warp * 512; l < warp * 512 + 512; l++) {
        const float* kr = kb + (size_t)l * Dc;
        float p = q0v * kr[lane] + q1v * kr[lane + 32];
#pragma unroll
        for (int off = 16; off > 0; off >>= 1)
            p += __shfl_xor_sync(0xffffffffu, p, off);
        p *= 0.125f;
        float mn = fmaxf(m, p);
        float c = expf(m - mn);
        float w = expf(p - mn);
        const float* vr = vb + (size_t)l * Dc;
        s  = s * c + w;
        a0 = a0 * c + w * vr[lane];
        a1 = a1 * c + w * vr[lane + 32];
        m = mn;
    }
    if (lane == 0) { wm[warp] = m; ws[warp] = s; }
    wa[warp][lane] = a0; wa[warp][lane + 32] = a1;
    __syncthreads();
    if (tid < 64) {
        float gm = fmaxf(fmaxf(wm[0], wm[1]), fmaxf(wm[2], wm[3]));
        float gs = 0.f, ga = 0.f;
#pragma unroll
        for (int w2 = 0; w2 < 4; w2++) {
            float f = expf(wm[w2] - gm);
            gs += ws[w2] * f;
            ga += wa[w2][tid] * f;
        }
        outred[((size_t)bh * TOPK + ui) * 64 + tid] = ga / gs;
    }
}

__global__ void init_bias_kernel(const float* __restrict__ bo, float* __restrict__ AO)
{
    float4 v = *(const float4*)(bo + threadIdx.x * 4);
    *(float4*)(AO + (size_t)blockIdx.x * Dc + threadIdx.x * 4) = v;
}

__global__ __launch_bounds__(256) void sparse_proj_kernel(
    const float* __restrict__ outred, const int* __restrict__ Mtop,
    const float* __restrict__ wo, float* __restrict__ AO)
{
    int ui = blockIdx.x, bh = blockIdx.y;
    int b = bh >> 4, h = bh & 15;
    int l = Mtop[bh * TOPK + ui];
    __shared__ float r[64];
    int tid = threadIdx.x;
    if (tid < 64) r[tid] = outred[((size_t)bh * TOPK + ui) * 64 + tid];
    __syncthreads();
    float a0 = 0.f, a1 = 0.f, a2 = 0.f, a3 = 0.f;
    const float* w = wo + (size_t)h * 64 * Dc + tid;
#pragma unroll 8
    for (int e = 0; e < 64; e++) {
        float re = r[e];
        const float* wr = w + (size_t)e * Dc;
        a0 = fmaf(re, wr[0],   a0);
        a1 = fmaf(re, wr[256], a1);
        a2 = fmaf(re, wr[512], a2);
        a3 = fmaf(re, wr[768], a3);
    }
    float* dst = AO + ((size_t)b * Lc + l) * Dc + tid;
    atomicAdd(dst,       a0);
    atomicAdd(dst + 256, a1);
    atomicAdd(dst + 512, a2);
    atomicAdd(dst + 768, a3);
}

__global__ __launch_bounds__(256) void add_ln_kernel(
    const float* __restrict__ X, const float* __restrict__ Y,
    const float* __restrict__ g, const float* __restrict__ be, float* __restrict__ out)
{
    int row = blockIdx.x, tid = threadIdx.x;
    __shared__ float red[256];
    float v[4];
    float s = 0.f;
#pragma unroll
    for (int c = 0; c < 4; c++) {
        size_t i = (size_t)row * Dc + tid + c * 256;
        v[c] = X[i] + Y[i];
        s += v[c];
    }
    red[tid] = s; __syncthreads();
    for (int st = 128; st > 0; st >>= 1) {
        if (tid < st) red[tid] += red[tid + st];
        __syncthreads();
    }
    float mean = red[0] * (1.f / 1024.f);
    __syncthreads();
    float s2 = 0.f;
#pragma unroll
    for (int c = 0; c < 4; c++) { float t = v[c] - mean; s2 = fmaf(t, t, s2); }
    red[tid] = s2; __syncthreads();
    for (int st = 128; st > 0; st >>= 1) {
        if (tid < st) red[tid] += red[tid + st];
        __syncthreads();
    }
    float var = red[0] * (1.f / 1024.f);
    float rstd = 1.0f / sqrtf(var + 1e-12f);
#pragma unroll
    for (int c = 0; c < 4; c++) {
        int col = tid + c * 256;
        out[(size_t)row * Dc + col] = g[col] * ((v[c] - mean) * rstd) + be[col];
    }
}

// ---------------- launch ---------------------------------------------------
extern "C" void kernel_launch(void* const* d_in, const int* in_sizes, int n_in,
                              void* d_out, int out_size)
{
    const float* x   = (const float*)d_in[0];
    const float* wq  = (const float*)d_in[1];
    const float* bq  = (const float*)d_in[2];
    const float* wk  = (const float*)d_in[3];
    const float* bk  = (const float*)d_in[4];
    const float* wv  = (const float*)d_in[5];
    const float* bv  = (const float*)d_in[6];
    const float* wo  = (const float*)d_in[7];
    const float* bo  = (const float*)d_in[8];
    const float* w1  = (const float*)d_in[9];
    const float* b1  = (const float*)d_in[10];
    const float* w2  = (const float*)d_in[11];
    const float* b2  = (const float*)d_in[12];
    const float* ga1 = (const float*)d_in[13];
    const float* be1 = (const float*)d_in[14];
    const float* ga2 = (const float*)d_in[15];
    const float* be2 = (const float*)d_in[16];
    const int*   idx = (const int*)d_in[17];
    float* out = (float*)d_out;

    float *Q, *K, *V, *Qh, *Ql, *Xh, *Xl, *X1h, *X1l, *Y1h, *Y1l;
    float *Ksh, *Ksl, *AO, *X1, *Y1, *Y2, *Mv, *Or;
    float *Wqh, *Wql, *Wkh, *Wkl, *Wvh, *Wvl, *W1h, *W1l, *W2h, *W2l;
    int* Mt;
    cudaGetSymbolAddress((void**)&Q,   g_Q);
    cudaGetSymbolAddress((void**)&K,   g_K);
    cudaGetSymbolAddress((void**)&V,   g_V);
    cudaGetSymbolAddress((void**)&Qh,  g_Qh);
    cudaGetSymbolAddress((void**)&Ql,  g_Ql);
    cudaGetSymbolAddress((void**)&Xh,  g_Xh);
    cudaGetSymbolAddress((void**)&Xl,  g_Xl);
    cudaGetSymbolAddress((void**)&X1h, g_X1h);
    cudaGetSymbolAddress((void**)&X1l, g_X1l);
    cudaGetSymbolAddress((void**)&Y1h, g_Y1h);
    cudaGetSymbolAddress((void**)&Y1l, g_Y1l);
    cudaGetSymbolAddress((void**)&Ksh, g_Ksh);
    cudaGetSymbolAddress((void**)&Ksl, g_Ksl);
    cudaGetSymbolAddress((void**)&AO,  g_AO);
    cudaGetSymbolAddress((void**)&X1,  g_X1);
    cudaGetSymbolAddress((void**)&Y1,  g_Y1);
    cudaGetSymbolAddress((void**)&Y2,  g_Y2);
    cudaGetSymbolAddress((void**)&Mv,  g_M);
    cudaGetSymbolAddress((void**)&Mt,  g_Mtop);
    cudaGetSymbolAddress((void**)&Or,  g_Or);
    cudaGetSymbolAddress((void**)&Wqh, g_Wqh);
    cudaGetSymbolAddress((void**)&Wql, g_Wql);
    cudaGetSymbolAddress((void**)&Wkh, g_Wkh);
    cudaGetSymbolAddress((void**)&Wkl, g_Wkl);
    cudaGetSymbolAddress((void**)&Wvh, g_Wvh);
    cudaGetSymbolAddress((void**)&Wvl, g_Wvl);
    cudaGetSymbolAddress((void**)&W1h, g_W1h);
    cudaGetSymbolAddress((void**)&W1l, g_W1l);
    cudaGetSymbolAddress((void**)&W2h, g_W2h);
    cudaGetSymbolAddress((void**)&W2l, g_W2l);

    cudaFuncSetAttribute(gemm_mma, cudaFuncAttributeMaxDynamicSharedMemorySize, 2 * GST);
    cudaFuncSetAttribute(qk_mma,   cudaFuncAttributeMaxDynamicSharedMemorySize, 141312);

    dim3 t32x8(32, 8);
    tsplit_kernel<<<dim3(Dc / 32, Dc / 32), t32x8>>>(wq, Wqh, Wql, Dc, Dc);
    tsplit_kernel<<<dim3(Dc / 32, Dc / 32), t32x8>>>(wk, Wkh, Wkl, Dc, Dc);
    tsplit_kernel<<<dim3(Dc / 32, Dc / 32), t32x8>>>(wv, Wvh, Wvl, Dc, Dc);
    tsplit_kernel<<<dim3(Fc / 32, Dc / 32), t32x8>>>(w1, W1h, W1l, Dc, Fc);
    tsplit_kernel<<<dim3(Dc / 32, Fc / 32), t32x8>>>(w2, W2h, W2l, Fc, Dc);

    split_kernel<<<(MR * Dc / 4) / 256, 256>>>(x, Xh, Xl);

    gemm_mma<<<dim3(8, 64), 256, 2 * GST>>>(Xh, Xl, Wqh, Wql, bq, Q, Dc, Dc, 0);
    gemm_mma<<<dim3(8, 64), 256, 2 * GST>>>(Xh, Xl, Wkh, Wkl, bk, K, Dc, Dc, 0);
    gemm_mma<<<dim3(8, 64), 256, 2 * GST>>>(Xh, Xl, Wvh, Wvl, bv, V, Dc, Dc, 0);

    split_kernel<<<(MR * Dc / 4) / 256, 256>>>(Q, Qh, Ql);
    gather_split_kernel<<<dim3(Uc, Bc), 256>>>(K, idx, Ksh, Ksl);

    qk_mma<<<dim3(Lc / 128, BHc), 256, 141312>>>(Qh, Ql, Ksh, Ksl, Mv);
    topk_kernel<<<BHc, 256>>>(Mv, Mt);

    sparse_attn_kernel<<<dim3(TOPK, BHc), 128>>>(Q, K, V, Mt, Or);

    init_bias_kernel<<<MR, 256>>>(bo, AO);
    sparse_proj_kernel<<<dim3(TOPK, BHc), 256>>>(Or, Mt, wo, AO);

    add_ln_kernel<<<MR, 256>>>(x, AO, ga1, be1, X1);

    split_kernel<<<(MR * Dc / 4) / 256, 256>>>(X1, X1h, X1l);
    gemm_mma<<<dim3(32, 64), 256, 2 * GST>>>(X1h, X1l, W1h, W1l, b1, Y1, Dc, Fc, 1);

    split_kernel<<<(MR * Fc / 4) / 256, 256>>>(Y1, Y1h, Y1l);
    gemm_mma<<<dim3(8, 64), 256, 2 * GST>>>(Y1h, Y1l, W2h, W2l, b2, Y2, Fc, Dc, 0);

    add_ln_kernel<<<MR, 256>>>(X1, Y2, ga2, be2, out);
}